// round 2
// baseline (speedup 1.0000x reference)
#include <cuda_runtime.h>
#include <cuda_bf16.h>
#include <cstddef>

// Problem constants
#define BATCH   2
#define SEQ     2048
#define DIM     1024
#define HEADS   16
#define DHEAD   64
#define INNER   1024          // HEADS*DHEAD
#define ROWS    (BATCH*SEQ)   // 4096
#define QKV_N   (3*INNER)     // 3072
#define EPS     1e-5f
#define QSCALE  0.125f        // DHEAD^-0.5

// ---------------- scratch (static device globals; no runtime allocation) ----
__device__ float g_xn  [ (size_t)ROWS * DIM   ];   // 16 MB
__device__ float g_qkv [ (size_t)ROWS * QKV_N ];   // 48 MB
__device__ float g_att [ (size_t)ROWS * INNER ];   // 16 MB
__device__ float g_proj[ (size_t)ROWS * DIM   ];   // 16 MB

// ---------------- LayerNorm (one row per block, 256 thr, 4 floats/thr) -----
__device__ __forceinline__ void ln_body(const float* __restrict__ in,
                                        const float* __restrict__ gamma,
                                        const float* __restrict__ beta,
                                        float* __restrict__ out)
{
    const int row = blockIdx.x;
    const float* xr = in + (size_t)row * DIM;
    const int t = threadIdx.x;

    float4 xv = *(const float4*)(xr + t * 4);
    float sum = xv.x + xv.y + xv.z + xv.w;
    float sq  = xv.x*xv.x + xv.y*xv.y + xv.z*xv.z + xv.w*xv.w;

    #pragma unroll
    for (int o = 16; o > 0; o >>= 1) {
        sum += __shfl_xor_sync(0xffffffffu, sum, o);
        sq  += __shfl_xor_sync(0xffffffffu, sq,  o);
    }
    __shared__ float s1[8], s2[8];
    const int warp = t >> 5;
    if ((t & 31) == 0) { s1[warp] = sum; s2[warp] = sq; }
    __syncthreads();
    float tot = 0.f, totq = 0.f;
    #pragma unroll
    for (int w = 0; w < 8; w++) { tot += s1[w]; totq += s2[w]; }

    const float mean = tot * (1.0f / DIM);
    const float var  = totq * (1.0f / DIM) - mean * mean;
    const float inv  = rsqrtf(var + EPS);

    float4 gv = *(const float4*)(gamma + t * 4);
    float4 bv = *(const float4*)(beta  + t * 4);
    float4 ov;
    ov.x = (xv.x - mean) * inv * gv.x + bv.x;
    ov.y = (xv.y - mean) * inv * gv.y + bv.y;
    ov.z = (xv.z - mean) * inv * gv.z + bv.z;
    ov.w = (xv.w - mean) * inv * gv.w + bv.w;
    *(float4*)(out + (size_t)row * DIM + t * 4) = ov;
}

__global__ __launch_bounds__(256) void ln1_kernel(const float* __restrict__ x,
                                                  const float* __restrict__ g,
                                                  const float* __restrict__ b)
{ ln_body(x, g, b, g_xn); }

__global__ __launch_bounds__(256) void ln2_kernel(const float* __restrict__ g,
                                                  const float* __restrict__ b,
                                                  float* __restrict__ out)
{ ln_body(g_proj, g, b, out); }

// ---------------- fp32 tiled GEMM:  C[M,N] = A[M,K] * B[K,N] ----------------
// BM=128, BN=64, BK=16, 256 threads, each thread computes 8x4.
template<int M, int N, int K>
__device__ __forceinline__ void gemm_body(const float* __restrict__ A,
                                          const float* __restrict__ B,
                                          float* __restrict__ C)
{
    constexpr int BM = 128, BN = 64, BK = 16;
    __shared__ float As[BK][132];   // [k][m], padded (132*4 = 528B, 16B aligned)
    __shared__ float Bs[BK][68];    // [k][n], padded (272B rows)

    const int tid = threadIdx.x;
    const int tx = tid & 15;        // 0..15 -> n
    const int ty = tid >> 4;        // 0..15 -> m
    const int bm = blockIdx.y * BM;
    const int bn = blockIdx.x * BN;

    float acc[8][4];
    #pragma unroll
    for (int i = 0; i < 8; i++)
        #pragma unroll
        for (int j = 0; j < 4; j++) acc[i][j] = 0.f;

    for (int k0 = 0; k0 < K; k0 += BK) {
        // A tile: 128x16 floats = 512 float4; 2 per thread; stored transposed
        #pragma unroll
        for (int tldr = 0; tldr < 2; tldr++) {
            int idx = tid + tldr * 256;       // 0..511
            int row = idx >> 2;
            int c4  = (idx & 3) * 4;
            float4 v = *(const float4*)(A + (size_t)(bm + row) * K + k0 + c4);
            As[c4 + 0][row] = v.x;
            As[c4 + 1][row] = v.y;
            As[c4 + 2][row] = v.z;
            As[c4 + 3][row] = v.w;
        }
        // B tile: 16x64 floats = 256 float4; 1 per thread
        {
            int row = tid >> 4;
            int c4  = (tid & 15) * 4;
            float4 v = *(const float4*)(B + (size_t)(k0 + row) * N + bn + c4);
            *(float4*)&Bs[row][c4] = v;
        }
        __syncthreads();

        #pragma unroll
        for (int kk = 0; kk < BK; kk++) {
            float4 a0 = *(const float4*)&As[kk][ty * 8];
            float4 a1 = *(const float4*)&As[kk][ty * 8 + 4];
            float4 b0 = *(const float4*)&Bs[kk][tx * 4];
            float a[8] = {a0.x,a0.y,a0.z,a0.w,a1.x,a1.y,a1.z,a1.w};
            float bb[4] = {b0.x,b0.y,b0.z,b0.w};
            #pragma unroll
            for (int i = 0; i < 8; i++)
                #pragma unroll
                for (int j = 0; j < 4; j++)
                    acc[i][j] = fmaf(a[i], bb[j], acc[i][j]);
        }
        __syncthreads();
    }

    #pragma unroll
    for (int i = 0; i < 8; i++) {
        float4 v = {acc[i][0], acc[i][1], acc[i][2], acc[i][3]};
        *(float4*)(C + (size_t)(bm + ty * 8 + i) * N + bn + tx * 4) = v;
    }
}

__global__ __launch_bounds__(256) void gemm_qkv_kernel(const float* __restrict__ w)
{ gemm_body<ROWS, QKV_N, DIM>(g_xn, w, g_qkv); }

__global__ __launch_bounds__(256) void gemm_out_kernel(const float* __restrict__ w)
{ gemm_body<ROWS, DIM, INNER>(g_att, w, g_proj); }

// ---------------- causal ReLU attention (no softmax => pure streaming) ------
// Block: 64 query rows of one (b,h). Loop over key tiles j<=i:
//   S = (Q*scale) K^T ; S = causal_relu(S) ; O += S V
// smem tiles stride 65 (scalar LDS, conflict-light).
#define TPAD 65
#define ATTN_SMEM (3 * 64 * TPAD * 4)

__global__ __launch_bounds__(256) void attn_kernel()
{
    extern __shared__ float sm[];
    float* Qs = sm;                   // 64 x 65
    float* Ks = sm + 64 * TPAD;       // 64 x 65 (reused for V)
    float* Ss = sm + 2 * 64 * TPAD;   // 64 x 65

    const int tid = threadIdx.x;
    const int tx = tid & 15;          // key/dhead tile col group
    const int ty = tid >> 4;          // query row group

    const int qt = blockIdx.x;        // 0..31 query tile
    const int bh = blockIdx.y;        // 0..31
    const int b  = bh >> 4;
    const int h  = bh & 15;

    const float* qb = g_qkv + (size_t)b * SEQ * QKV_N + h * DHEAD;
    const float* kb = qb + INNER;
    const float* vb = qb + 2 * INNER;
    const int qi0 = qt * 64;

    // load Q tile (scaled)
    #pragma unroll
    for (int t = 0; t < 4; t++) {
        int idx = tid + t * 256;            // 0..1023
        int row = idx >> 4;
        int c4  = (idx & 15) * 4;
        float4 v = *(const float4*)(qb + (size_t)(qi0 + row) * QKV_N + c4);
        float* dst = &Qs[row * TPAD + c4];
        dst[0] = v.x * QSCALE; dst[1] = v.y * QSCALE;
        dst[2] = v.z * QSCALE; dst[3] = v.w * QSCALE;
    }

    float o[4][4];
    #pragma unroll
    for (int i = 0; i < 4; i++)
        #pragma unroll
        for (int d = 0; d < 4; d++) o[i][d] = 0.f;

    for (int kt = 0; kt <= qt; kt++) {
        __syncthreads();   // Ks free (prev O done) / Q visible
        // load K tile
        #pragma unroll
        for (int t = 0; t < 4; t++) {
            int idx = tid + t * 256;
            int row = idx >> 4;
            int c4  = (idx & 15) * 4;
            float4 v = *(const float4*)(kb + (size_t)(kt * 64 + row) * QKV_N + c4);
            float* dst = &Ks[row * TPAD + c4];
            dst[0] = v.x; dst[1] = v.y; dst[2] = v.z; dst[3] = v.w;
        }
        __syncthreads();

        // S = Q K^T (4x4 fragment per thread)
        float s[4][4];
        #pragma unroll
        for (int i = 0; i < 4; i++)
            #pragma unroll
            for (int j = 0; j < 4; j++) s[i][j] = 0.f;

        #pragma unroll 4
        for (int d = 0; d < DHEAD; d++) {
            float qv[4], kv[4];
            #pragma unroll
            for (int i = 0; i < 4; i++) qv[i] = Qs[(ty * 4 + i) * TPAD + d];
            #pragma unroll
            for (int j = 0; j < 4; j++) kv[j] = Ks[(tx * 4 + j) * TPAD + d];
            #pragma unroll
            for (int i = 0; i < 4; i++)
                #pragma unroll
                for (int j = 0; j < 4; j++)
                    s[i][j] = fmaf(qv[i], kv[j], s[i][j]);
        }

        // causal relu + stage to smem
        #pragma unroll
        for (int i = 0; i < 4; i++) {
            int gi = qi0 + ty * 4 + i;
            #pragma unroll
            for (int j = 0; j < 4; j++) {
                int gj = kt * 64 + tx * 4 + j;
                float v = (gj <= gi) ? fmaxf(s[i][j], 0.f) : 0.f;
                Ss[(ty * 4 + i) * TPAD + tx * 4 + j] = v;
            }
        }
        __syncthreads();

        // load V tile into Ks
        #pragma unroll
        for (int t = 0; t < 4; t++) {
            int idx = tid + t * 256;
            int row = idx >> 4;
            int c4  = (idx & 15) * 4;
            float4 v = *(const float4*)(vb + (size_t)(kt * 64 + row) * QKV_N + c4);
            float* dst = &Ks[row * TPAD + c4];
            dst[0] = v.x; dst[1] = v.y; dst[2] = v.z; dst[3] = v.w;
        }
        __syncthreads();

        // O += S V
        #pragma unroll 4
        for (int j = 0; j < 64; j++) {
            float sv[4], vv[4];
            #pragma unroll
            for (int i = 0; i < 4; i++) sv[i] = Ss[(ty * 4 + i) * TPAD + j];
            #pragma unroll
            for (int d = 0; d < 4; d++) vv[d] = Ks[j * TPAD + tx * 4 + d];
            #pragma unroll
            for (int i = 0; i < 4; i++)
                #pragma unroll
                for (int d = 0; d < 4; d++)
                    o[i][d] = fmaf(sv[i], vv[d], o[i][d]);
        }
    }

    // store O into [rows, h*64+d] layout
    float* ob = g_att + (size_t)(b * SEQ + qi0) * INNER + h * DHEAD;
    #pragma unroll
    for (int i = 0; i < 4; i++) {
        float4 v = {o[i][0], o[i][1], o[i][2], o[i][3]};
        *(float4*)(ob + (size_t)(ty * 4 + i) * INNER + tx * 4) = v;
    }
}

// ---------------- launch ----------------------------------------------------
extern "C" void kernel_launch(void* const* d_in, const int* in_sizes, int n_in,
                              void* d_out, int out_size)
{
    const float* x     = (const float*)d_in[0];
    const float* ln1_g = (const float*)d_in[1];
    const float* ln1_b = (const float*)d_in[2];
    const float* w_qkv = (const float*)d_in[3];
    const float* w_out = (const float*)d_in[4];
    const float* ln2_g = (const float*)d_in[5];
    const float* ln2_b = (const float*)d_in[6];
    float* out = (float*)d_out;

    cudaFuncSetAttribute(attn_kernel,
                         cudaFuncAttributeMaxDynamicSharedMemorySize, ATTN_SMEM);

    ln1_kernel<<<ROWS, 256>>>(x, ln1_g, ln1_b);
    gemm_qkv_kernel<<<dim3(QKV_N / 64, ROWS / 128), 256>>>(w_qkv);
    attn_kernel<<<dim3(SEQ / 64, BATCH * HEADS), 256, ATTN_SMEM>>>();
    gemm_out_kernel<<<dim3(DIM / 64, ROWS / 128), 256>>>(w_out);
    ln2_kernel<<<ROWS, 256>>>(ln2_g, ln2_b, out);
}

// round 4
// speedup vs baseline: 1.3882x; 1.3882x over previous
#include <cuda_runtime.h>
#include <cstdint>
#include <cstddef>

// Problem constants
#define BATCH   2
#define SEQ     2048
#define DIM     1024
#define HEADS   16
#define DHEAD   64
#define INNER   1024
#define ROWS    (BATCH*SEQ)   // 4096
#define QKV_N   (3*INNER)     // 3072
#define EPS     1e-5f
#define QSCALE  0.125f

// ---------------- scratch (static device globals) ---------------------------
__device__ float g_xn  [(size_t)ROWS * DIM  ];
__device__ float g_qkv [(size_t)ROWS * QKV_N];
__device__ float g_att [(size_t)ROWS * INNER];
__device__ float g_proj[(size_t)ROWS * DIM  ];
__device__ float g_wq  [(size_t)DIM * QKV_N ];   // tf32-rounded w_qkv
__device__ float g_wo  [(size_t)INNER * DIM ];   // tf32-rounded w_out

// ---------------- helpers ----------------------------------------------------
__device__ __forceinline__ float rnd_tf32(float x) {
    uint32_t u; asm("cvt.rna.tf32.f32 %0, %1;" : "=r"(u) : "f"(x));
    return __uint_as_float(u);
}
__device__ __forceinline__ uint32_t smem_u32(const void* p) {
    uint32_t a;
    asm("{ .reg .u64 t; cvta.to.shared.u64 t, %1; cvt.u32.u64 %0, t; }"
        : "=r"(a) : "l"(p));
    return a;
}
__device__ __forceinline__ void cpa16(uint32_t dst, const float* src) {
    asm volatile("cp.async.cg.shared.global [%0], [%1], 16;" :: "r"(dst), "l"(src));
}
__device__ __forceinline__ void cpa_commit() {
    asm volatile("cp.async.commit_group;" ::: "memory");
}
template<int N> __device__ __forceinline__ void cpa_wait() {
    asm volatile("cp.async.wait_group %0;" :: "n"(N) : "memory");
}
__device__ __forceinline__ void mma_tf32(float& d0, float& d1, float& d2, float& d3,
                                         uint32_t a0, uint32_t a1, uint32_t a2, uint32_t a3,
                                         uint32_t b0, uint32_t b1) {
    asm volatile("mma.sync.aligned.m16n8k8.row.col.f32.tf32.tf32.f32 "
                 "{%0,%1,%2,%3},{%4,%5,%6,%7},{%8,%9},{%0,%1,%2,%3};"
                 : "+f"(d0), "+f"(d1), "+f"(d2), "+f"(d3)
                 : "r"(a0), "r"(a1), "r"(a2), "r"(a3), "r"(b0), "r"(b1));
}

// ---------------- LayerNorm (optionally rounds output to tf32 grid) ---------
template<bool ROUND>
__device__ __forceinline__ void ln_body(const float* __restrict__ in,
                                        const float* __restrict__ gamma,
                                        const float* __restrict__ beta,
                                        float* __restrict__ out)
{
    const int row = blockIdx.x;
    const float* xr = in + (size_t)row * DIM;
    const int t = threadIdx.x;

    float4 xv = *(const float4*)(xr + t * 4);
    float sum = xv.x + xv.y + xv.z + xv.w;
    float sq  = xv.x*xv.x + xv.y*xv.y + xv.z*xv.z + xv.w*xv.w;
    #pragma unroll
    for (int o = 16; o > 0; o >>= 1) {
        sum += __shfl_xor_sync(0xffffffffu, sum, o);
        sq  += __shfl_xor_sync(0xffffffffu, sq,  o);
    }
    __shared__ float s1[8], s2[8];
    const int warp = t >> 5;
    if ((t & 31) == 0) { s1[warp] = sum; s2[warp] = sq; }
    __syncthreads();
    float tot = 0.f, totq = 0.f;
    #pragma unroll
    for (int w = 0; w < 8; w++) { tot += s1[w]; totq += s2[w]; }
    const float mean = tot * (1.0f / DIM);
    const float var  = totq * (1.0f / DIM) - mean * mean;
    const float inv  = rsqrtf(var + EPS);
    float4 gv = *(const float4*)(gamma + t * 4);
    float4 bv = *(const float4*)(beta  + t * 4);
    float4 ov;
    ov.x = (xv.x - mean) * inv * gv.x + bv.x;
    ov.y = (xv.y - mean) * inv * gv.y + bv.y;
    ov.z = (xv.z - mean) * inv * gv.z + bv.z;
    ov.w = (xv.w - mean) * inv * gv.w + bv.w;
    if (ROUND) {
        ov.x = rnd_tf32(ov.x); ov.y = rnd_tf32(ov.y);
        ov.z = rnd_tf32(ov.z); ov.w = rnd_tf32(ov.w);
    }
    *(float4*)(out + (size_t)row * DIM + t * 4) = ov;
}
__global__ __launch_bounds__(256) void ln1_kernel(const float* __restrict__ x,
                                                  const float* __restrict__ g,
                                                  const float* __restrict__ b)
{ ln_body<true>(x, g, b, g_xn); }
__global__ __launch_bounds__(256) void ln2_kernel(const float* __restrict__ g,
                                                  const float* __restrict__ b,
                                                  float* __restrict__ out)
{ ln_body<false>(g_proj, g, b, out); }

// ---------------- elementwise tf32 rounding (weights) -----------------------
__global__ __launch_bounds__(256) void round_tf32_kernel(const float* __restrict__ in,
                                                         float* __restrict__ out, int n4)
{
    int i = blockIdx.x * blockDim.x + threadIdx.x;
    if (i < n4) {
        float4 v = ((const float4*)in)[i];
        v.x = rnd_tf32(v.x); v.y = rnd_tf32(v.y);
        v.z = rnd_tf32(v.z); v.w = rnd_tf32(v.w);
        ((float4*)out)[i] = v;
    }
}

// ---------------- tf32 HMMA GEMM: C[M,Ntot] = A[M,K] * B[K,Ntot] -------------
// BM=BN=128, BK=32, 256 threads (8 warps as 2x4), warp tile 64x32.
// smem: A [128][36] padded, B [32][132] padded, 2-stage cp.async pipeline.
#define GBM 128
#define GBN 128
#define GBK 32
#define SA_STRIDE 36
#define SB_STRIDE 132
#define SA_FLOATS (128 * SA_STRIDE)   // 4608
#define SB_FLOATS (GBK * SB_STRIDE)   // 4224
#define GEMM_SMEM ((2 * SA_FLOATS + 2 * SB_FLOATS) * 4)   // 70656 B

__global__ __launch_bounds__(256, 2) void gemm_tf32_kernel(
    const float* __restrict__ A, const float* __restrict__ B,
    float* __restrict__ C, int Ntot, int K)
{
    extern __shared__ float sm[];
    float* sA = sm;                       // [2][SA_FLOATS]
    float* sB = sm + 2 * SA_FLOATS;       // [2][SB_FLOATS]
    const uint32_t sAu = smem_u32(sA);
    const uint32_t sBu = smem_u32(sB);

    const int tid = threadIdx.x;
    const int lane = tid & 31;
    const int wid = tid >> 5;
    const int warpM = wid >> 2;           // 0..1
    const int warpN = wid & 3;            // 0..3
    const int bm = blockIdx.y * GBM;
    const int bn = blockIdx.x * GBN;
    const int NCH = K / GBK;

    // staging coords: A thread covers row am, 4 float4 at cols ah*16 + j*4
    const int am = tid & 127;
    const int ah = tid >> 7;              // 0..1
    const float* aG = A + (size_t)(bm + am) * K + ah * 16;
    const uint32_t aDst = sAu + (uint32_t)(am * SA_STRIDE + ah * 16) * 4;

    // B thread covers k-row bk, 4 float4 at cols bf*4 + j*32
    const int bk = tid >> 3;              // 0..31
    const int bf = tid & 7;
    const float* bG = B + (size_t)bk * Ntot + bn + bf * 4;
    const uint32_t bDst = sBu + (uint32_t)(bk * SB_STRIDE + bf * 4) * 4;

    float acc[4][4][4];
    #pragma unroll
    for (int i = 0; i < 4; i++)
        #pragma unroll
        for (int j = 0; j < 4; j++)
            #pragma unroll
            for (int r = 0; r < 4; r++) acc[i][j][r] = 0.f;

    // pipeline issue
    #define GEMM_ISSUE(c, buf) do {                                           \
        const float* _ag = aG + (c) * GBK;                                     \
        const uint32_t _ad = aDst + (buf) * (SA_FLOATS * 4);                   \
        _Pragma("unroll")                                                      \
        for (int j = 0; j < 4; j++) cpa16(_ad + j * 16, _ag + j * 4);          \
        const float* _bg = bG + (size_t)(c) * GBK * Ntot;                      \
        const uint32_t _bd = bDst + (buf) * (SB_FLOATS * 4);                   \
        _Pragma("unroll")                                                      \
        for (int j = 0; j < 4; j++) cpa16(_bd + j * 128, _bg + j * 32);        \
    } while (0)

    GEMM_ISSUE(0, 0); cpa_commit();
    GEMM_ISSUE(1, 1); cpa_commit();

    const int arow = warpM * 64 + (lane >> 2);
    const int alo  = lane & 3;
    const int bcol = warpN * 32 + (lane >> 2);

    for (int c = 0; c < NCH; c++) {
        cpa_wait<1>();
        __syncthreads();

        const int buf = c & 1;
        const float* aS = sA + buf * SA_FLOATS;
        const float* bS = sB + buf * SB_FLOATS;

        #pragma unroll
        for (int ks = 0; ks < 4; ks++) {
            uint32_t af[4][4];
            #pragma unroll
            for (int mt = 0; mt < 4; mt++) {
                const float* p = aS + (arow + mt * 16) * SA_STRIDE + ks * 8 + alo;
                af[mt][0] = __float_as_uint(p[0]);
                af[mt][1] = __float_as_uint(p[8 * SA_STRIDE]);
                af[mt][2] = __float_as_uint(p[4]);
                af[mt][3] = __float_as_uint(p[8 * SA_STRIDE + 4]);
            }
            uint32_t bfr[4][2];
            #pragma unroll
            for (int nt = 0; nt < 4; nt++) {
                const float* p = bS + (ks * 8 + alo) * SB_STRIDE + bcol + nt * 8;
                bfr[nt][0] = __float_as_uint(p[0]);
                bfr[nt][1] = __float_as_uint(p[4 * SB_STRIDE]);
            }
            #pragma unroll
            for (int mt = 0; mt < 4; mt++)
                #pragma unroll
                for (int nt = 0; nt < 4; nt++)
                    mma_tf32(acc[mt][nt][0], acc[mt][nt][1],
                             acc[mt][nt][2], acc[mt][nt][3],
                             af[mt][0], af[mt][1], af[mt][2], af[mt][3],
                             bfr[nt][0], bfr[nt][1]);
        }
        __syncthreads();

        if (c + 2 < NCH) GEMM_ISSUE(c + 2, buf);
        cpa_commit();
    }

    // epilogue
    #pragma unroll
    for (int mt = 0; mt < 4; mt++) {
        #pragma unroll
        for (int nt = 0; nt < 4; nt++) {
            const int row = bm + warpM * 64 + mt * 16 + (lane >> 2);
            const int col = bn + warpN * 32 + nt * 8 + (lane & 3) * 2;
            float2 v0 = {acc[mt][nt][0], acc[mt][nt][1]};
            float2 v1 = {acc[mt][nt][2], acc[mt][nt][3]};
            *(float2*)(C + (size_t)row * Ntot + col) = v0;
            *(float2*)(C + (size_t)(row + 8) * Ntot + col) = v1;
        }
    }
    #undef GEMM_ISSUE
}

// ---------------- causal ReLU attention (fp32 SIMT) -------------------------
#define TPAD 65
#define ATTN_SMEM (3 * 64 * TPAD * 4)

__global__ __launch_bounds__(256) void attn_kernel()
{
    extern __shared__ float smf[];
    float* Qs = smf;
    float* Ks = smf + 64 * TPAD;
    float* Ss = smf + 2 * 64 * TPAD;

    const int tid = threadIdx.x;
    const int tx = tid & 15;
    const int ty = tid >> 4;
    const int qt = blockIdx.x;
    const int bh = blockIdx.y;
    const int b  = bh >> 4;
    const int h  = bh & 15;

    const float* qb = g_qkv + (size_t)b * SEQ * QKV_N + h * DHEAD;
    const float* kb = qb + INNER;
    const float* vb = qb + 2 * INNER;
    const int qi0 = qt * 64;

    #pragma unroll
    for (int t = 0; t < 4; t++) {
        int idx = tid + t * 256;
        int row = idx >> 4;
        int c4  = (idx & 15) * 4;
        float4 v = *(const float4*)(qb + (size_t)(qi0 + row) * QKV_N + c4);
        float* dst = &Qs[row * TPAD + c4];
        dst[0] = v.x * QSCALE; dst[1] = v.y * QSCALE;
        dst[2] = v.z * QSCALE; dst[3] = v.w * QSCALE;
    }

    float o[4][4];
    #pragma unroll
    for (int i = 0; i < 4; i++)
        #pragma unroll
        for (int d = 0; d < 4; d++) o[i][d] = 0.f;

    for (int kt = 0; kt <= qt; kt++) {
        __syncthreads();
        #pragma unroll
        for (int t = 0; t < 4; t++) {
            int idx = tid + t * 256;
            int row = idx >> 4;
            int c4  = (idx & 15) * 4;
            float4 v = *(const float4*)(kb + (size_t)(kt * 64 + row) * QKV_N + c4);
            float* dst = &Ks[row * TPAD + c4];
            dst[0] = v.x; dst[1] = v.y; dst[2] = v.z; dst[3] = v.w;
        }
        __syncthreads();

        float s[4][4];
        #pragma unroll
        for (int i = 0; i < 4; i++)
            #pragma unroll
            for (int j = 0; j < 4; j++) s[i][j] = 0.f;

        #pragma unroll 4
        for (int d = 0; d < DHEAD; d++) {
            float qv[4], kv[4];
            #pragma unroll
            for (int i = 0; i < 4; i++) qv[i] = Qs[(ty * 4 + i) * TPAD + d];
            #pragma unroll
            for (int j = 0; j < 4; j++) kv[j] = Ks[(tx * 4 + j) * TPAD + d];
            #pragma unroll
            for (int i = 0; i < 4; i++)
                #pragma unroll
                for (int j = 0; j < 4; j++)
                    s[i][j] = fmaf(qv[i], kv[j], s[i][j]);
        }

        #pragma unroll
        for (int i = 0; i < 4; i++) {
            int gi = qi0 + ty * 4 + i;
            #pragma unroll
            for (int j = 0; j < 4; j++) {
                int gj = kt * 64 + tx * 4 + j;
                float v = (gj <= gi) ? fmaxf(s[i][j], 0.f) : 0.f;
                Ss[(ty * 4 + i) * TPAD + tx * 4 + j] = v;
            }
        }
        __syncthreads();

        #pragma unroll
        for (int t = 0; t < 4; t++) {
            int idx = tid + t * 256;
            int row = idx >> 4;
            int c4  = (idx & 15) * 4;
            float4 v = *(const float4*)(vb + (size_t)(kt * 64 + row) * QKV_N + c4);
            float* dst = &Ks[row * TPAD + c4];
            dst[0] = v.x; dst[1] = v.y; dst[2] = v.z; dst[3] = v.w;
        }
        __syncthreads();

        #pragma unroll 4
        for (int j = 0; j < 64; j++) {
            float sv[4], vv[4];
            #pragma unroll
            for (int i = 0; i < 4; i++) sv[i] = Ss[(ty * 4 + i) * TPAD + j];
            #pragma unroll
            for (int d = 0; d < 4; d++) vv[d] = Ks[j * TPAD + tx * 4 + d];
            #pragma unroll
            for (int i = 0; i < 4; i++)
                #pragma unroll
                for (int d = 0; d < 4; d++)
                    o[i][d] = fmaf(sv[i], vv[d], o[i][d]);
        }
    }

    // round to tf32 grid here: g_att feeds the tf32 out-projection GEMM
    float* ob = g_att + (size_t)(b * SEQ + qi0) * INNER + h * DHEAD;
    #pragma unroll
    for (int i = 0; i < 4; i++) {
        float4 v = {rnd_tf32(o[i][0]), rnd_tf32(o[i][1]),
                    rnd_tf32(o[i][2]), rnd_tf32(o[i][3])};
        *(float4*)(ob + (size_t)(ty * 4 + i) * INNER + tx * 4) = v;
    }
}

// ---------------- launch -----------------------------------------------------
extern "C" void kernel_launch(void* const* d_in, const int* in_sizes, int n_in,
                              void* d_out, int out_size)
{
    const float* x     = (const float*)d_in[0];
    const float* ln1_g = (const float*)d_in[1];
    const float* ln1_b = (const float*)d_in[2];
    const float* w_qkv = (const float*)d_in[3];
    const float* w_out = (const float*)d_in[4];
    const float* ln2_g = (const float*)d_in[5];
    const float* ln2_b = (const float*)d_in[6];
    float* out = (float*)d_out;

    cudaFuncSetAttribute(attn_kernel,
                         cudaFuncAttributeMaxDynamicSharedMemorySize, ATTN_SMEM);
    cudaFuncSetAttribute(gemm_tf32_kernel,
                         cudaFuncAttributeMaxDynamicSharedMemorySize, GEMM_SMEM);

    float* wq;   cudaGetSymbolAddress((void**)&wq,   g_wq);
    float* wo;   cudaGetSymbolAddress((void**)&wo,   g_wo);
    float* xn;   cudaGetSymbolAddress((void**)&xn,   g_xn);
    float* qkv;  cudaGetSymbolAddress((void**)&qkv,  g_qkv);
    float* att;  cudaGetSymbolAddress((void**)&att,  g_att);
    float* proj; cudaGetSymbolAddress((void**)&proj, g_proj);

    ln1_kernel<<<ROWS, 256>>>(x, ln1_g, ln1_b);

    {
        int n4 = (DIM * QKV_N) / 4;
        round_tf32_kernel<<<(n4 + 255) / 256, 256>>>(w_qkv, wq, n4);
    }
    {
        int n4 = (INNER * DIM) / 4;
        round_tf32_kernel<<<(n4 + 255) / 256, 256>>>(w_out, wo, n4);
    }

    gemm_tf32_kernel<<<dim3(QKV_N / GBN, ROWS / GBM), 256, GEMM_SMEM>>>(
        xn, wq, qkv, QKV_N, DIM);

    attn_kernel<<<dim3(SEQ / 64, BATCH * HEADS), 256, ATTN_SMEM>>>();

    gemm_tf32_kernel<<<dim3(DIM / GBN, ROWS / GBM), 256, GEMM_SMEM>>>(
        att, wo, proj, DIM, INNER);

    ln2_kernel<<<ROWS, 256>>>(ln2_g, ln2_b, out);
}

// round 5
// speedup vs baseline: 2.3377x; 1.6840x over previous
#include <cuda_runtime.h>
#include <cstdint>
#include <cstddef>

// Problem constants
#define BATCH   2
#define SEQ     2048
#define DIM     1024
#define HEADS   16
#define DHEAD   64
#define INNER   1024
#define ROWS    (BATCH*SEQ)   // 4096
#define QKV_N   (3*INNER)     // 3072
#define EPS     1e-5f
#define QSCALE  0.125f

// ---------------- scratch (static device globals) ---------------------------
__device__ float g_xn  [(size_t)ROWS * DIM  ];
__device__ float g_qkv [(size_t)ROWS * QKV_N];
__device__ float g_att [(size_t)ROWS * INNER];
__device__ float g_proj[(size_t)ROWS * DIM  ];
__device__ float g_wq  [(size_t)DIM * QKV_N ];
__device__ float g_wo  [(size_t)INNER * DIM ];

// ---------------- helpers ----------------------------------------------------
__device__ __forceinline__ float rnd_tf32(float x) {
    uint32_t u; asm("cvt.rna.tf32.f32 %0, %1;" : "=r"(u) : "f"(x));
    return __uint_as_float(u);
}
__device__ __forceinline__ uint32_t smem_u32(const void* p) {
    uint32_t a;
    asm("{ .reg .u64 t; cvta.to.shared.u64 t, %1; cvt.u32.u64 %0, t; }"
        : "=r"(a) : "l"(p));
    return a;
}
__device__ __forceinline__ void cpa16(uint32_t dst, const float* src) {
    asm volatile("cp.async.cg.shared.global [%0], [%1], 16;" :: "r"(dst), "l"(src));
}
__device__ __forceinline__ void cpa_commit() {
    asm volatile("cp.async.commit_group;" ::: "memory");
}
template<int N> __device__ __forceinline__ void cpa_wait() {
    asm volatile("cp.async.wait_group %0;" :: "n"(N) : "memory");
}
__device__ __forceinline__ void mma_tf32(float& d0, float& d1, float& d2, float& d3,
                                         uint32_t a0, uint32_t a1, uint32_t a2, uint32_t a3,
                                         uint32_t b0, uint32_t b1) {
    asm volatile("mma.sync.aligned.m16n8k8.row.col.f32.tf32.tf32.f32 "
                 "{%0,%1,%2,%3},{%4,%5,%6,%7},{%8,%9},{%0,%1,%2,%3};"
                 : "+f"(d0), "+f"(d1), "+f"(d2), "+f"(d3)
                 : "r"(a0), "r"(a1), "r"(a2), "r"(a3), "r"(b0), "r"(b1));
}

// ---------------- LayerNorm ---------------------------------------------------
template<bool ROUND>
__device__ __forceinline__ void ln_body(const float* __restrict__ in,
                                        const float* __restrict__ gamma,
                                        const float* __restrict__ beta,
                                        float* __restrict__ out)
{
    const int row = blockIdx.x;
    const float* xr = in + (size_t)row * DIM;
    const int t = threadIdx.x;

    float4 xv = *(const float4*)(xr + t * 4);
    float sum = xv.x + xv.y + xv.z + xv.w;
    float sq  = xv.x*xv.x + xv.y*xv.y + xv.z*xv.z + xv.w*xv.w;
    #pragma unroll
    for (int o = 16; o > 0; o >>= 1) {
        sum += __shfl_xor_sync(0xffffffffu, sum, o);
        sq  += __shfl_xor_sync(0xffffffffu, sq,  o);
    }
    __shared__ float s1[8], s2[8];
    const int warp = t >> 5;
    if ((t & 31) == 0) { s1[warp] = sum; s2[warp] = sq; }
    __syncthreads();
    float tot = 0.f, totq = 0.f;
    #pragma unroll
    for (int w = 0; w < 8; w++) { tot += s1[w]; totq += s2[w]; }
    const float mean = tot * (1.0f / DIM);
    const float var  = totq * (1.0f / DIM) - mean * mean;
    const float inv  = rsqrtf(var + EPS);
    float4 gv = *(const float4*)(gamma + t * 4);
    float4 bv = *(const float4*)(beta  + t * 4);
    float4 ov;
    ov.x = (xv.x - mean) * inv * gv.x + bv.x;
    ov.y = (xv.y - mean) * inv * gv.y + bv.y;
    ov.z = (xv.z - mean) * inv * gv.z + bv.z;
    ov.w = (xv.w - mean) * inv * gv.w + bv.w;
    if (ROUND) {
        ov.x = rnd_tf32(ov.x); ov.y = rnd_tf32(ov.y);
        ov.z = rnd_tf32(ov.z); ov.w = rnd_tf32(ov.w);
    }
    *(float4*)(out + (size_t)row * DIM + t * 4) = ov;
}
__global__ __launch_bounds__(256) void ln1_kernel(const float* __restrict__ x,
                                                  const float* __restrict__ g,
                                                  const float* __restrict__ b)
{ ln_body<true>(x, g, b, g_xn); }
__global__ __launch_bounds__(256) void ln2_kernel(const float* __restrict__ g,
                                                  const float* __restrict__ b,
                                                  float* __restrict__ out)
{ ln_body<false>(g_proj, g, b, out); }

// ---------------- elementwise tf32 rounding (weights) -----------------------
__global__ __launch_bounds__(256) void round_tf32_kernel(const float* __restrict__ in,
                                                         float* __restrict__ out, int n4)
{
    int i = blockIdx.x * blockDim.x + threadIdx.x;
    if (i < n4) {
        float4 v = ((const float4*)in)[i];
        v.x = rnd_tf32(v.x); v.y = rnd_tf32(v.y);
        v.z = rnd_tf32(v.z); v.w = rnd_tf32(v.w);
        ((float4*)out)[i] = v;
    }
}

// ---------------- tf32 HMMA GEMM: C[M,Ntot] = A[M,K] * B[K,Ntot] -------------
#define GBM 128
#define GBN 128
#define GBK 32
#define SA_STRIDE 36
#define SB_STRIDE 136
#define SA_FLOATS (128 * SA_STRIDE)
#define SB_FLOATS (GBK * SB_STRIDE)
#define GEMM_SMEM ((2 * SA_FLOATS + 2 * SB_FLOATS) * 4)

template<bool RND>
__global__ __launch_bounds__(256, 2) void gemm_tf32_kernel(
    const float* __restrict__ A, const float* __restrict__ B,
    float* __restrict__ C, int Ntot, int K)
{
    extern __shared__ float sm[];
    float* sA = sm;
    float* sB = sm + 2 * SA_FLOATS;
    const uint32_t sAu = smem_u32(sA);
    const uint32_t sBu = smem_u32(sB);

    const int tid = threadIdx.x;
    const int lane = tid & 31;
    const int wid = tid >> 5;
    const int warpM = wid >> 2;
    const int warpN = wid & 3;
    const int bm = blockIdx.y * GBM;
    const int bn = blockIdx.x * GBN;
    const int NCH = K / GBK;

    const int am = tid & 127;
    const int ah = tid >> 7;
    const float* aG = A + (size_t)(bm + am) * K + ah * 16;
    const uint32_t aDst = sAu + (uint32_t)(am * SA_STRIDE + ah * 16) * 4;

    const int bk = tid >> 3;
    const int bf = tid & 7;
    const float* bG = B + (size_t)bk * Ntot + bn + bf * 4;
    const uint32_t bDst = sBu + (uint32_t)(bk * SB_STRIDE + bf * 4) * 4;

    float acc[4][4][4];
    #pragma unroll
    for (int i = 0; i < 4; i++)
        #pragma unroll
        for (int j = 0; j < 4; j++)
            #pragma unroll
            for (int r = 0; r < 4; r++) acc[i][j][r] = 0.f;

    #define GEMM_ISSUE(c, buf) do {                                           \
        const float* _ag = aG + (c) * GBK;                                     \
        const uint32_t _ad = aDst + (buf) * (SA_FLOATS * 4);                   \
        _Pragma("unroll")                                                      \
        for (int j = 0; j < 4; j++) cpa16(_ad + j * 16, _ag + j * 4);          \
        const float* _bg = bG + (size_t)(c) * GBK * Ntot;                      \
        const uint32_t _bd = bDst + (buf) * (SB_FLOATS * 4);                   \
        _Pragma("unroll")                                                      \
        for (int j = 0; j < 4; j++) cpa16(_bd + j * 128, _bg + j * 32);        \
    } while (0)

    GEMM_ISSUE(0, 0); cpa_commit();
    GEMM_ISSUE(1, 1); cpa_commit();

    const int arow = warpM * 64 + (lane >> 2);
    const int alo  = lane & 3;
    const int bcol = warpN * 32 + (lane >> 2);

    for (int c = 0; c < NCH; c++) {
        cpa_wait<1>();
        __syncthreads();

        const int buf = c & 1;
        const float* aS = sA + buf * SA_FLOATS;
        const float* bS = sB + buf * SB_FLOATS;

        #pragma unroll
        for (int ks = 0; ks < 4; ks++) {
            uint32_t af[4][4];
            #pragma unroll
            for (int mt = 0; mt < 4; mt++) {
                const float* p = aS + (arow + mt * 16) * SA_STRIDE + ks * 8 + alo;
                af[mt][0] = __float_as_uint(p[0]);
                af[mt][1] = __float_as_uint(p[8 * SA_STRIDE]);
                af[mt][2] = __float_as_uint(p[4]);
                af[mt][3] = __float_as_uint(p[8 * SA_STRIDE + 4]);
            }
            uint32_t bfr[4][2];
            #pragma unroll
            for (int nt = 0; nt < 4; nt++) {
                const float* p = bS + (ks * 8 + alo) * SB_STRIDE + bcol + nt * 8;
                bfr[nt][0] = __float_as_uint(p[0]);
                bfr[nt][1] = __float_as_uint(p[4 * SB_STRIDE]);
            }
            #pragma unroll
            for (int mt = 0; mt < 4; mt++)
                #pragma unroll
                for (int nt = 0; nt < 4; nt++)
                    mma_tf32(acc[mt][nt][0], acc[mt][nt][1],
                             acc[mt][nt][2], acc[mt][nt][3],
                             af[mt][0], af[mt][1], af[mt][2], af[mt][3],
                             bfr[nt][0], bfr[nt][1]);
        }
        __syncthreads();

        if (c + 2 < NCH) GEMM_ISSUE(c + 2, buf);
        cpa_commit();
    }

    #pragma unroll
    for (int mt = 0; mt < 4; mt++) {
        #pragma unroll
        for (int nt = 0; nt < 4; nt++) {
            const int row = bm + warpM * 64 + mt * 16 + (lane >> 2);
            const int col = bn + warpN * 32 + nt * 8 + (lane & 3) * 2;
            float2 v0, v1;
            if (RND) {
                v0 = make_float2(rnd_tf32(acc[mt][nt][0]), rnd_tf32(acc[mt][nt][1]));
                v1 = make_float2(rnd_tf32(acc[mt][nt][2]), rnd_tf32(acc[mt][nt][3]));
            } else {
                v0 = make_float2(acc[mt][nt][0], acc[mt][nt][1]);
                v1 = make_float2(acc[mt][nt][2], acc[mt][nt][3]);
            }
            *(float2*)(C + (size_t)row * Ntot + col) = v0;
            *(float2*)(C + (size_t)(row + 8) * Ntot + col) = v1;
        }
    }
    #undef GEMM_ISSUE
}

// ---------------- tensor-core causal ReLU attention --------------------------
// 64-query tile per CTA, 128 threads (4 warps, m16 each).
// S = Q K^T via tf32 mma; relu+mask; S split hi/lo (exact); O += Shi*V + Slo*V.
// Q,K,V already on tf32 grid (qkv GEMM epilogue rounds) -> MMA truncation lossless.
#define AQ_ST 68
#define AK_ST 68
#define AV_ST 72
#define AS_ST 68
#define OFF_Q  0
#define OFF_K  4352                 // + buf*4352 (double buffered)
#define OFF_V  13056
#define OFF_SH 17664
#define OFF_SL 22016
#define ATTN_FLOATS 26368
#define ATTN_SMEM (ATTN_FLOATS * 4) // 105472 B

__global__ __launch_bounds__(128) void attn_mma_kernel()
{
    extern __shared__ float sm[];
    const uint32_t smu = smem_u32(sm);
    const int tid  = threadIdx.x;
    const int lane = tid & 31;
    const int wid  = tid >> 5;
    const int ly = lane >> 2;
    const int lx = lane & 3;

    const int qt = 31 - blockIdx.x;     // longest tiles first
    const int bh = blockIdx.y;
    const int b  = bh >> 4;
    const int h  = bh & 15;
    const int qi0 = qt * 64;

    const float* qbase = g_qkv + (size_t)b * SEQ * QKV_N + h * DHEAD;
    const float* kbase = qbase + INNER;
    const float* vbase = qbase + 2 * INNER;

    const int ldr = tid >> 1;           // row this thread stages
    const int ldc = (tid & 1) * 32;     // col offset (32 floats = 8 float4)

    #define ISSUE_K(kt_, buf_) do {                                            \
        const float* _s = kbase + (size_t)((kt_) * 64 + ldr) * QKV_N + ldc;     \
        uint32_t _d = smu + (uint32_t)(OFF_K + (buf_) * 4352 + ldr * AK_ST + ldc) * 4; \
        _Pragma("unroll")                                                       \
        for (int j = 0; j < 8; j++) cpa16(_d + j * 16, _s + j * 4);             \
    } while (0)
    #define ISSUE_V(kt_) do {                                                  \
        const float* _s = vbase + (size_t)((kt_) * 64 + ldr) * QKV_N + ldc;     \
        uint32_t _d = smu + (uint32_t)(OFF_V + ldr * AV_ST + ldc) * 4;          \
        _Pragma("unroll")                                                       \
        for (int j = 0; j < 8; j++) cpa16(_d + j * 16, _s + j * 4);             \
    } while (0)

    // prefetch K(0), stage Q (scaled; scale=2^-3 keeps tf32 grid exact)
    ISSUE_K(0, 0); cpa_commit();
    {
        const float* src = qbase + (size_t)(qi0 + ldr) * QKV_N + ldc;
        float* dst = sm + OFF_Q + ldr * AQ_ST + ldc;
        #pragma unroll
        for (int j = 0; j < 8; j++) {
            float4 v = *(const float4*)(src + j * 4);
            v.x *= QSCALE; v.y *= QSCALE; v.z *= QSCALE; v.w *= QSCALE;
            *(float4*)(dst + j * 4) = v;
        }
    }

    float oacc[8][4];
    #pragma unroll
    for (int nt = 0; nt < 8; nt++)
        #pragma unroll
        for (int r = 0; r < 4; r++) oacc[nt][r] = 0.f;

    const float* Qw  = sm + OFF_Q  + (wid * 16) * AQ_ST;
    float* shw = sm + OFF_SH + (wid * 16 + ly) * AS_ST;
    float* slw = sm + OFF_SL + (wid * 16 + ly) * AS_ST;
    const float* shr = sm + OFF_SH + (wid * 16) * AS_ST;
    const float* slr = sm + OFF_SL + (wid * 16) * AS_ST;
    const int qrow = qi0 + wid * 16 + ly;

    for (int kt = 0; kt <= qt; kt++) {
        cpa_wait<0>();
        __syncthreads();            // K(kt) visible; V buffer free; Q visible (kt=0)

        ISSUE_V(kt); cpa_commit();
        if (kt < qt) { ISSUE_K(kt + 1, (kt + 1) & 1); cpa_commit(); }

        // ---- S = Q K^T
        const float* Kc = sm + OFF_K + (kt & 1) * 4352;
        float sacc[8][4];
        #pragma unroll
        for (int nt = 0; nt < 8; nt++)
            #pragma unroll
            for (int r = 0; r < 4; r++) sacc[nt][r] = 0.f;

        #pragma unroll
        for (int ks = 0; ks < 8; ks++) {
            const float* ap = Qw + ly * AQ_ST + ks * 8 + lx;
            uint32_t a0 = __float_as_uint(ap[0]);
            uint32_t a1 = __float_as_uint(ap[8 * AQ_ST]);
            uint32_t a2 = __float_as_uint(ap[4]);
            uint32_t a3 = __float_as_uint(ap[8 * AQ_ST + 4]);
            #pragma unroll
            for (int nt = 0; nt < 8; nt++) {
                const float* bp = Kc + (nt * 8 + ly) * AK_ST + ks * 8 + lx;
                uint32_t b0 = __float_as_uint(bp[0]);
                uint32_t b1 = __float_as_uint(bp[4]);
                mma_tf32(sacc[nt][0], sacc[nt][1], sacc[nt][2], sacc[nt][3],
                         a0, a1, a2, a3, b0, b1);
            }
        }

        // ---- causal relu + hi/lo split -> smem (warp-private rows)
        #pragma unroll
        for (int nt = 0; nt < 8; nt++) {
            int j0 = kt * 64 + nt * 8 + 2 * lx;
            float v0 = (j0     <= qrow    ) ? fmaxf(sacc[nt][0], 0.f) : 0.f;
            float v1 = (j0 + 1 <= qrow    ) ? fmaxf(sacc[nt][1], 0.f) : 0.f;
            float v2 = (j0     <= qrow + 8) ? fmaxf(sacc[nt][2], 0.f) : 0.f;
            float v3 = (j0 + 1 <= qrow + 8) ? fmaxf(sacc[nt][3], 0.f) : 0.f;
            float h0 = rnd_tf32(v0), h1 = rnd_tf32(v1);
            float h2 = rnd_tf32(v2), h3 = rnd_tf32(v3);
            *(float2*)(shw + nt * 8 + 2 * lx)              = make_float2(h0, h1);
            *(float2*)(shw + 8 * AS_ST + nt * 8 + 2 * lx)  = make_float2(h2, h3);
            *(float2*)(slw + nt * 8 + 2 * lx)              =
                make_float2(rnd_tf32(v0 - h0), rnd_tf32(v1 - h1));
            *(float2*)(slw + 8 * AS_ST + nt * 8 + 2 * lx)  =
                make_float2(rnd_tf32(v2 - h2), rnd_tf32(v3 - h3));
        }
        __syncwarp();

        if (kt < qt) cpa_wait<1>(); else cpa_wait<0>();
        __syncthreads();            // V visible to all warps

        // ---- O += Shi*V + Slo*V
        const float* Vc = sm + OFF_V;
        #pragma unroll
        for (int ks = 0; ks < 8; ks++) {
            const float* hp = shr + ly * AS_ST + ks * 8 + lx;
            const float* lp = slr + ly * AS_ST + ks * 8 + lx;
            uint32_t ah0 = __float_as_uint(hp[0]);
            uint32_t ah1 = __float_as_uint(hp[8 * AS_ST]);
            uint32_t ah2 = __float_as_uint(hp[4]);
            uint32_t ah3 = __float_as_uint(hp[8 * AS_ST + 4]);
            uint32_t al0 = __float_as_uint(lp[0]);
            uint32_t al1 = __float_as_uint(lp[8 * AS_ST]);
            uint32_t al2 = __float_as_uint(lp[4]);
            uint32_t al3 = __float_as_uint(lp[8 * AS_ST + 4]);
            #pragma unroll
            for (int nt = 0; nt < 8; nt++) {
                const float* bp = Vc + (ks * 8 + lx) * AV_ST + nt * 8 + ly;
                uint32_t b0 = __float_as_uint(bp[0]);
                uint32_t b1 = __float_as_uint(bp[4 * AV_ST]);
                mma_tf32(oacc[nt][0], oacc[nt][1], oacc[nt][2], oacc[nt][3],
                         ah0, ah1, ah2, ah3, b0, b1);
                mma_tf32(oacc[nt][0], oacc[nt][1], oacc[nt][2], oacc[nt][3],
                         al0, al1, al2, al3, b0, b1);
            }
        }
    }

    // ---- store O (tf32-rounded: feeds tf32 out-projection)
    float* ob = g_att + (size_t)(b * SEQ + qi0 + wid * 16 + ly) * INNER + h * DHEAD;
    #pragma unroll
    for (int nt = 0; nt < 8; nt++) {
        *(float2*)(ob + nt * 8 + 2 * lx) =
            make_float2(rnd_tf32(oacc[nt][0]), rnd_tf32(oacc[nt][1]));
        *(float2*)(ob + (size_t)8 * INNER + nt * 8 + 2 * lx) =
            make_float2(rnd_tf32(oacc[nt][2]), rnd_tf32(oacc[nt][3]));
    }
    #undef ISSUE_K
    #undef ISSUE_V
}

// ---------------- launch -----------------------------------------------------
extern "C" void kernel_launch(void* const* d_in, const int* in_sizes, int n_in,
                              void* d_out, int out_size)
{
    const float* x     = (const float*)d_in[0];
    const float* ln1_g = (const float*)d_in[1];
    const float* ln1_b = (const float*)d_in[2];
    const float* w_qkv = (const float*)d_in[3];
    const float* w_out = (const float*)d_in[4];
    const float* ln2_g = (const float*)d_in[5];
    const float* ln2_b = (const float*)d_in[6];
    float* out = (float*)d_out;

    cudaFuncSetAttribute(attn_mma_kernel,
                         cudaFuncAttributeMaxDynamicSharedMemorySize, ATTN_SMEM);
    cudaFuncSetAttribute(gemm_tf32_kernel<true>,
                         cudaFuncAttributeMaxDynamicSharedMemorySize, GEMM_SMEM);
    cudaFuncSetAttribute(gemm_tf32_kernel<false>,
                         cudaFuncAttributeMaxDynamicSharedMemorySize, GEMM_SMEM);

    float* wq;   cudaGetSymbolAddress((void**)&wq,   g_wq);
    float* wo;   cudaGetSymbolAddress((void**)&wo,   g_wo);
    float* xn;   cudaGetSymbolAddress((void**)&xn,   g_xn);
    float* qkv;  cudaGetSymbolAddress((void**)&qkv,  g_qkv);
    float* att;  cudaGetSymbolAddress((void**)&att,  g_att);
    float* proj; cudaGetSymbolAddress((void**)&proj, g_proj);

    ln1_kernel<<<ROWS, 256>>>(x, ln1_g, ln1_b);

    {
        int n4 = (DIM * QKV_N) / 4;
        round_tf32_kernel<<<(n4 + 255) / 256, 256>>>(w_qkv, wq, n4);
    }
    {
        int n4 = (INNER * DIM) / 4;
        round_tf32_kernel<<<(n4 + 255) / 256, 256>>>(w_out, wo, n4);
    }

    // qkv GEMM rounds its output to the tf32 grid (Q,K,V consumed by tf32 MMAs)
    gemm_tf32_kernel<true><<<dim3(QKV_N / GBN, ROWS / GBM), 256, GEMM_SMEM>>>(
        xn, wq, qkv, QKV_N, DIM);

    attn_mma_kernel<<<dim3(32, BATCH * HEADS), 128, ATTN_SMEM>>>();

    gemm_tf32_kernel<false><<<dim3(DIM / GBN, ROWS / GBM), 256, GEMM_SMEM>>>(
        att, wo, proj, DIM, INNER);

    ln2_kernel<<<ROWS, 256>>>(ln2_g, ln2_b, out);
}

// round 6
// speedup vs baseline: 2.5131x; 1.0750x over previous
#include <cuda_runtime.h>
#include <cstdint>
#include <cstddef>

// Problem constants
#define BATCH   2
#define SEQ     2048
#define DIM     1024
#define HEADS   16
#define DHEAD   64
#define INNER   1024
#define ROWS    (BATCH*SEQ)   // 4096
#define QKV_N   (3*INNER)     // 3072
#define EPS     1e-5f
#define QSCALE  0.125f

// ---------------- scratch (static device globals) ---------------------------
__device__ float g_xn  [(size_t)ROWS * DIM  ];
__device__ float g_qkv [(size_t)ROWS * QKV_N];
__device__ float g_att [(size_t)ROWS * INNER];
__device__ float g_proj[(size_t)ROWS * DIM  ];
__device__ float g_wq  [(size_t)DIM * QKV_N ];
__device__ float g_wo  [(size_t)INNER * DIM ];

// ---------------- helpers ----------------------------------------------------
__device__ __forceinline__ float rnd_tf32(float x) {
    uint32_t u; asm("cvt.rna.tf32.f32 %0, %1;" : "=r"(u) : "f"(x));
    return __uint_as_float(u);
}
__device__ __forceinline__ uint32_t smem_u32(const void* p) {
    uint32_t a;
    asm("{ .reg .u64 t; cvta.to.shared.u64 t, %1; cvt.u32.u64 %0, t; }"
        : "=r"(a) : "l"(p));
    return a;
}
__device__ __forceinline__ void cpa16(uint32_t dst, const float* src) {
    asm volatile("cp.async.cg.shared.global [%0], [%1], 16;" :: "r"(dst), "l"(src));
}
__device__ __forceinline__ void cpa_commit() {
    asm volatile("cp.async.commit_group;" ::: "memory");
}
template<int N> __device__ __forceinline__ void cpa_wait() {
    asm volatile("cp.async.wait_group %0;" :: "n"(N) : "memory");
}
__device__ __forceinline__ void mma_tf32(float& d0, float& d1, float& d2, float& d3,
                                         uint32_t a0, uint32_t a1, uint32_t a2, uint32_t a3,
                                         uint32_t b0, uint32_t b1) {
    asm volatile("mma.sync.aligned.m16n8k8.row.col.f32.tf32.tf32.f32 "
                 "{%0,%1,%2,%3},{%4,%5,%6,%7},{%8,%9},{%0,%1,%2,%3};"
                 : "+f"(d0), "+f"(d1), "+f"(d2), "+f"(d3)
                 : "r"(a0), "r"(a1), "r"(a2), "r"(a3), "r"(b0), "r"(b1));
}

// ---------------- LayerNorm ---------------------------------------------------
template<bool ROUND>
__device__ __forceinline__ void ln_body(const float* __restrict__ in,
                                        const float* __restrict__ gamma,
                                        const float* __restrict__ beta,
                                        float* __restrict__ out)
{
    const int row = blockIdx.x;
    const float* xr = in + (size_t)row * DIM;
    const int t = threadIdx.x;

    float4 xv = *(const float4*)(xr + t * 4);
    float sum = xv.x + xv.y + xv.z + xv.w;
    float sq  = xv.x*xv.x + xv.y*xv.y + xv.z*xv.z + xv.w*xv.w;
    #pragma unroll
    for (int o = 16; o > 0; o >>= 1) {
        sum += __shfl_xor_sync(0xffffffffu, sum, o);
        sq  += __shfl_xor_sync(0xffffffffu, sq,  o);
    }
    __shared__ float s1[8], s2[8];
    const int warp = t >> 5;
    if ((t & 31) == 0) { s1[warp] = sum; s2[warp] = sq; }
    __syncthreads();
    float tot = 0.f, totq = 0.f;
    #pragma unroll
    for (int w = 0; w < 8; w++) { tot += s1[w]; totq += s2[w]; }
    const float mean = tot * (1.0f / DIM);
    const float var  = totq * (1.0f / DIM) - mean * mean;
    const float inv  = rsqrtf(var + EPS);
    float4 gv = *(const float4*)(gamma + t * 4);
    float4 bv = *(const float4*)(beta  + t * 4);
    float4 ov;
    ov.x = (xv.x - mean) * inv * gv.x + bv.x;
    ov.y = (xv.y - mean) * inv * gv.y + bv.y;
    ov.z = (xv.z - mean) * inv * gv.z + bv.z;
    ov.w = (xv.w - mean) * inv * gv.w + bv.w;
    if (ROUND) {
        ov.x = rnd_tf32(ov.x); ov.y = rnd_tf32(ov.y);
        ov.z = rnd_tf32(ov.z); ov.w = rnd_tf32(ov.w);
    }
    *(float4*)(out + (size_t)row * DIM + t * 4) = ov;
}
__global__ __launch_bounds__(256) void ln1_kernel(const float* __restrict__ x,
                                                  const float* __restrict__ g,
                                                  const float* __restrict__ b)
{ ln_body<true>(x, g, b, g_xn); }
__global__ __launch_bounds__(256) void ln2_kernel(const float* __restrict__ g,
                                                  const float* __restrict__ b,
                                                  float* __restrict__ out)
{ ln_body<false>(g_proj, g, b, out); }

// ---------------- elementwise tf32 rounding (weights) -----------------------
__global__ __launch_bounds__(256) void round_tf32_kernel(const float* __restrict__ in,
                                                         float* __restrict__ out, int n4)
{
    int i = blockIdx.x * blockDim.x + threadIdx.x;
    if (i < n4) {
        float4 v = ((const float4*)in)[i];
        v.x = rnd_tf32(v.x); v.y = rnd_tf32(v.y);
        v.z = rnd_tf32(v.z); v.w = rnd_tf32(v.w);
        ((float4*)out)[i] = v;
    }
}

// ---------------- tf32 HMMA GEMM: C[M,Ntot] = A[M,K] * B[K,Ntot] -------------
#define GBM 128
#define GBN 128
#define GBK 32
#define SA_STRIDE 36
#define SB_STRIDE 136
#define SA_FLOATS (128 * SA_STRIDE)
#define SB_FLOATS (GBK * SB_STRIDE)
#define GEMM_SMEM ((2 * SA_FLOATS + 2 * SB_FLOATS) * 4)

template<bool RND>
__global__ __launch_bounds__(256, 2) void gemm_tf32_kernel(
    const float* __restrict__ A, const float* __restrict__ B,
    float* __restrict__ C, int Ntot, int K)
{
    extern __shared__ float sm[];
    float* sA = sm;
    float* sB = sm + 2 * SA_FLOATS;
    const uint32_t sAu = smem_u32(sA);
    const uint32_t sBu = smem_u32(sB);

    const int tid = threadIdx.x;
    const int lane = tid & 31;
    const int wid = tid >> 5;
    const int warpM = wid >> 2;
    const int warpN = wid & 3;
    const int bm = blockIdx.y * GBM;
    const int bn = blockIdx.x * GBN;
    const int NCH = K / GBK;

    const int am = tid & 127;
    const int ah = tid >> 7;
    const float* aG = A + (size_t)(bm + am) * K + ah * 16;
    const uint32_t aDst = sAu + (uint32_t)(am * SA_STRIDE + ah * 16) * 4;

    const int bk = tid >> 3;
    const int bf = tid & 7;
    const float* bG = B + (size_t)bk * Ntot + bn + bf * 4;
    const uint32_t bDst = sBu + (uint32_t)(bk * SB_STRIDE + bf * 4) * 4;

    float acc[4][4][4];
    #pragma unroll
    for (int i = 0; i < 4; i++)
        #pragma unroll
        for (int j = 0; j < 4; j++)
            #pragma unroll
            for (int r = 0; r < 4; r++) acc[i][j][r] = 0.f;

    #define GEMM_ISSUE(c, buf) do {                                           \
        const float* _ag = aG + (c) * GBK;                                     \
        const uint32_t _ad = aDst + (buf) * (SA_FLOATS * 4);                   \
        _Pragma("unroll")                                                      \
        for (int j = 0; j < 4; j++) cpa16(_ad + j * 16, _ag + j * 4);          \
        const float* _bg = bG + (size_t)(c) * GBK * Ntot;                      \
        const uint32_t _bd = bDst + (buf) * (SB_FLOATS * 4);                   \
        _Pragma("unroll")                                                      \
        for (int j = 0; j < 4; j++) cpa16(_bd + j * 128, _bg + j * 32);        \
    } while (0)

    GEMM_ISSUE(0, 0); cpa_commit();
    GEMM_ISSUE(1, 1); cpa_commit();

    const int arow = warpM * 64 + (lane >> 2);
    const int alo  = lane & 3;
    const int bcol = warpN * 32 + (lane >> 2);

    for (int c = 0; c < NCH; c++) {
        cpa_wait<1>();
        __syncthreads();

        const int buf = c & 1;
        const float* aS = sA + buf * SA_FLOATS;
        const float* bS = sB + buf * SB_FLOATS;

        #pragma unroll
        for (int ks = 0; ks < 4; ks++) {
            uint32_t af[4][4];
            #pragma unroll
            for (int mt = 0; mt < 4; mt++) {
                const float* p = aS + (arow + mt * 16) * SA_STRIDE + ks * 8 + alo;
                af[mt][0] = __float_as_uint(p[0]);
                af[mt][1] = __float_as_uint(p[8 * SA_STRIDE]);
                af[mt][2] = __float_as_uint(p[4]);
                af[mt][3] = __float_as_uint(p[8 * SA_STRIDE + 4]);
            }
            uint32_t bfr[4][2];
            #pragma unroll
            for (int nt = 0; nt < 4; nt++) {
                const float* p = bS + (ks * 8 + alo) * SB_STRIDE + bcol + nt * 8;
                bfr[nt][0] = __float_as_uint(p[0]);
                bfr[nt][1] = __float_as_uint(p[4 * SB_STRIDE]);
            }
            #pragma unroll
            for (int mt = 0; mt < 4; mt++)
                #pragma unroll
                for (int nt = 0; nt < 4; nt++)
                    mma_tf32(acc[mt][nt][0], acc[mt][nt][1],
                             acc[mt][nt][2], acc[mt][nt][3],
                             af[mt][0], af[mt][1], af[mt][2], af[mt][3],
                             bfr[nt][0], bfr[nt][1]);
        }
        __syncthreads();

        if (c + 2 < NCH) GEMM_ISSUE(c + 2, buf);
        cpa_commit();
    }

    #pragma unroll
    for (int mt = 0; mt < 4; mt++) {
        #pragma unroll
        for (int nt = 0; nt < 4; nt++) {
            const int row = bm + warpM * 64 + mt * 16 + (lane >> 2);
            const int col = bn + warpN * 32 + nt * 8 + (lane & 3) * 2;
            float2 v0, v1;
            if (RND) {
                v0 = make_float2(rnd_tf32(acc[mt][nt][0]), rnd_tf32(acc[mt][nt][1]));
                v1 = make_float2(rnd_tf32(acc[mt][nt][2]), rnd_tf32(acc[mt][nt][3]));
            } else {
                v0 = make_float2(acc[mt][nt][0], acc[mt][nt][1]);
                v1 = make_float2(acc[mt][nt][2], acc[mt][nt][3]);
            }
            *(float2*)(C + (size_t)row * Ntot + col) = v0;
            *(float2*)(C + (size_t)(row + 8) * Ntot + col) = v1;
        }
    }
    #undef GEMM_ISSUE
}

// ---------------- tensor-core causal ReLU attention --------------------------
// 64-query tile per CTA, 128 threads (4 warps, m16 each).
// S = Q K^T via tf32 mma; relu(+mask on diagonal tile only); S rna-rounded;
// O += S*V (single term). Q,K,V are on the tf32 grid already.
#define AQ_ST 68
#define AK_ST 68
#define AV_ST 72
#define AS_ST 68
#define OFF_Q  0
#define OFF_K  4352                 // + buf*4352 (double buffered)
#define OFF_V  13056
#define OFF_SH 17664
#define ATTN_FLOATS 22016
#define ATTN_SMEM (ATTN_FLOATS * 4) // 88064 B

__global__ __launch_bounds__(128) void attn_mma_kernel()
{
    extern __shared__ float sm[];
    const uint32_t smu = smem_u32(sm);
    const int tid  = threadIdx.x;
    const int lane = tid & 31;
    const int wid  = tid >> 5;
    const int ly = lane >> 2;
    const int lx = lane & 3;

    const int qt = 31 - blockIdx.x;     // longest tiles first
    const int bh = blockIdx.y;
    const int b  = bh >> 4;
    const int h  = bh & 15;
    const int qi0 = qt * 64;

    const float* qbase = g_qkv + (size_t)b * SEQ * QKV_N + h * DHEAD;
    const float* kbase = qbase + INNER;
    const float* vbase = qbase + 2 * INNER;

    const int ldr = tid >> 1;           // row this thread stages
    const int ldc = (tid & 1) * 32;     // col offset (32 floats = 8 float4)

    #define ISSUE_K(kt_, buf_) do {                                            \
        const float* _s = kbase + (size_t)((kt_) * 64 + ldr) * QKV_N + ldc;     \
        uint32_t _d = smu + (uint32_t)(OFF_K + (buf_) * 4352 + ldr * AK_ST + ldc) * 4; \
        _Pragma("unroll")                                                       \
        for (int j = 0; j < 8; j++) cpa16(_d + j * 16, _s + j * 4);             \
    } while (0)
    #define ISSUE_V(kt_) do {                                                  \
        const float* _s = vbase + (size_t)((kt_) * 64 + ldr) * QKV_N + ldc;     \
        uint32_t _d = smu + (uint32_t)(OFF_V + ldr * AV_ST + ldc) * 4;          \
        _Pragma("unroll")                                                       \
        for (int j = 0; j < 8; j++) cpa16(_d + j * 16, _s + j * 4);             \
    } while (0)

    // prefetch K(0), stage Q (scaled; scale=2^-3 keeps tf32 grid exact)
    ISSUE_K(0, 0); cpa_commit();
    {
        const float* src = qbase + (size_t)(qi0 + ldr) * QKV_N + ldc;
        float* dst = sm + OFF_Q + ldr * AQ_ST + ldc;
        #pragma unroll
        for (int j = 0; j < 8; j++) {
            float4 v = *(const float4*)(src + j * 4);
            v.x *= QSCALE; v.y *= QSCALE; v.z *= QSCALE; v.w *= QSCALE;
            *(float4*)(dst + j * 4) = v;
        }
    }

    float oacc[8][4];
    #pragma unroll
    for (int nt = 0; nt < 8; nt++)
        #pragma unroll
        for (int r = 0; r < 4; r++) oacc[nt][r] = 0.f;

    const float* Qw  = sm + OFF_Q  + (wid * 16) * AQ_ST;
    float* shw = sm + OFF_SH + (wid * 16 + ly) * AS_ST;
    const float* shr = sm + OFF_SH + (wid * 16) * AS_ST;
    const int qrow = qi0 + wid * 16 + ly;

    for (int kt = 0; kt <= qt; kt++) {
        cpa_wait<0>();
        __syncthreads();            // K(kt) visible; V buffer free; Q visible (kt=0)

        ISSUE_V(kt); cpa_commit();
        if (kt < qt) { ISSUE_K(kt + 1, (kt + 1) & 1); cpa_commit(); }

        // ---- S = Q K^T
        const float* Kc = sm + OFF_K + (kt & 1) * 4352;
        float sacc[8][4];
        #pragma unroll
        for (int nt = 0; nt < 8; nt++)
            #pragma unroll
            for (int r = 0; r < 4; r++) sacc[nt][r] = 0.f;

        #pragma unroll
        for (int ks = 0; ks < 8; ks++) {
            const float* ap = Qw + ly * AQ_ST + ks * 8 + lx;
            uint32_t a0 = __float_as_uint(ap[0]);
            uint32_t a1 = __float_as_uint(ap[8 * AQ_ST]);
            uint32_t a2 = __float_as_uint(ap[4]);
            uint32_t a3 = __float_as_uint(ap[8 * AQ_ST + 4]);
            #pragma unroll
            for (int nt = 0; nt < 8; nt++) {
                const float* bp = Kc + (nt * 8 + ly) * AK_ST + ks * 8 + lx;
                uint32_t b0 = __float_as_uint(bp[0]);
                uint32_t b1 = __float_as_uint(bp[4]);
                mma_tf32(sacc[nt][0], sacc[nt][1], sacc[nt][2], sacc[nt][3],
                         a0, a1, a2, a3, b0, b1);
            }
        }

        // ---- relu (+ causal mask on the diagonal tile only), rna-round, store
        if (kt < qt) {
            #pragma unroll
            for (int nt = 0; nt < 8; nt++) {
                float h0 = rnd_tf32(fmaxf(sacc[nt][0], 0.f));
                float h1 = rnd_tf32(fmaxf(sacc[nt][1], 0.f));
                float h2 = rnd_tf32(fmaxf(sacc[nt][2], 0.f));
                float h3 = rnd_tf32(fmaxf(sacc[nt][3], 0.f));
                *(float2*)(shw + nt * 8 + 2 * lx)             = make_float2(h0, h1);
                *(float2*)(shw + 8 * AS_ST + nt * 8 + 2 * lx) = make_float2(h2, h3);
            }
        } else {
            #pragma unroll
            for (int nt = 0; nt < 8; nt++) {
                int j0 = kt * 64 + nt * 8 + 2 * lx;
                float v0 = (j0     <= qrow    ) ? fmaxf(sacc[nt][0], 0.f) : 0.f;
                float v1 = (j0 + 1 <= qrow    ) ? fmaxf(sacc[nt][1], 0.f) : 0.f;
                float v2 = (j0     <= qrow + 8) ? fmaxf(sacc[nt][2], 0.f) : 0.f;
                float v3 = (j0 + 1 <= qrow + 8) ? fmaxf(sacc[nt][3], 0.f) : 0.f;
                *(float2*)(shw + nt * 8 + 2 * lx) =
                    make_float2(rnd_tf32(v0), rnd_tf32(v1));
                *(float2*)(shw + 8 * AS_ST + nt * 8 + 2 * lx) =
                    make_float2(rnd_tf32(v2), rnd_tf32(v3));
            }
        }
        __syncwarp();

        if (kt < qt) cpa_wait<1>(); else cpa_wait<0>();
        __syncthreads();            // V visible to all warps

        // ---- O += S*V
        const float* Vc = sm + OFF_V;
        #pragma unroll
        for (int ks = 0; ks < 8; ks++) {
            const float* hp = shr + ly * AS_ST + ks * 8 + lx;
            uint32_t ah0 = __float_as_uint(hp[0]);
            uint32_t ah1 = __float_as_uint(hp[8 * AS_ST]);
            uint32_t ah2 = __float_as_uint(hp[4]);
            uint32_t ah3 = __float_as_uint(hp[8 * AS_ST + 4]);
            #pragma unroll
            for (int nt = 0; nt < 8; nt++) {
                const float* bp = Vc + (ks * 8 + lx) * AV_ST + nt * 8 + ly;
                uint32_t b0 = __float_as_uint(bp[0]);
                uint32_t b1 = __float_as_uint(bp[4 * AV_ST]);
                mma_tf32(oacc[nt][0], oacc[nt][1], oacc[nt][2], oacc[nt][3],
                         ah0, ah1, ah2, ah3, b0, b1);
            }
        }
    }

    // ---- store O (tf32-rounded: feeds tf32 out-projection)
    float* ob = g_att + (size_t)(b * SEQ + qi0 + wid * 16 + ly) * INNER + h * DHEAD;
    #pragma unroll
    for (int nt = 0; nt < 8; nt++) {
        *(float2*)(ob + nt * 8 + 2 * lx) =
            make_float2(rnd_tf32(oacc[nt][0]), rnd_tf32(oacc[nt][1]));
        *(float2*)(ob + (size_t)8 * INNER + nt * 8 + 2 * lx) =
            make_float2(rnd_tf32(oacc[nt][2]), rnd_tf32(oacc[nt][3]));
    }
    #undef ISSUE_K
    #undef ISSUE_V
}

// ---------------- launch -----------------------------------------------------
extern "C" void kernel_launch(void* const* d_in, const int* in_sizes, int n_in,
                              void* d_out, int out_size)
{
    const float* x     = (const float*)d_in[0];
    const float* ln1_g = (const float*)d_in[1];
    const float* ln1_b = (const float*)d_in[2];
    const float* w_qkv = (const float*)d_in[3];
    const float* w_out = (const float*)d_in[4];
    const float* ln2_g = (const float*)d_in[5];
    const float* ln2_b = (const float*)d_in[6];
    float* out = (float*)d_out;

    cudaFuncSetAttribute(attn_mma_kernel,
                         cudaFuncAttributeMaxDynamicSharedMemorySize, ATTN_SMEM);
    cudaFuncSetAttribute(gemm_tf32_kernel<true>,
                         cudaFuncAttributeMaxDynamicSharedMemorySize, GEMM_SMEM);
    cudaFuncSetAttribute(gemm_tf32_kernel<false>,
                         cudaFuncAttributeMaxDynamicSharedMemorySize, GEMM_SMEM);

    float* wq;   cudaGetSymbolAddress((void**)&wq,   g_wq);
    float* wo;   cudaGetSymbolAddress((void**)&wo,   g_wo);
    float* xn;   cudaGetSymbolAddress((void**)&xn,   g_xn);
    float* qkv;  cudaGetSymbolAddress((void**)&qkv,  g_qkv);
    float* att;  cudaGetSymbolAddress((void**)&att,  g_att);
    float* proj; cudaGetSymbolAddress((void**)&proj, g_proj);

    ln1_kernel<<<ROWS, 256>>>(x, ln1_g, ln1_b);

    {
        int n4 = (DIM * QKV_N) / 4;
        round_tf32_kernel<<<(n4 + 255) / 256, 256>>>(w_qkv, wq, n4);
    }
    {
        int n4 = (INNER * DIM) / 4;
        round_tf32_kernel<<<(n4 + 255) / 256, 256>>>(w_out, wo, n4);
    }

    // qkv GEMM rounds its output to the tf32 grid (Q,K,V consumed by tf32 MMAs)
    gemm_tf32_kernel<true><<<dim3(QKV_N / GBN, ROWS / GBM), 256, GEMM_SMEM>>>(
        xn, wq, qkv, QKV_N, DIM);

    attn_mma_kernel<<<dim3(32, BATCH * HEADS), 128, ATTN_SMEM>>>();

    gemm_tf32_kernel<false><<<dim3(DIM / GBN, ROWS / GBM), 256, GEMM_SMEM>>>(
        att, wo, proj, DIM, INNER);

    ln2_kernel<<<ROWS, 256>>>(ln2_g, ln2_b, out);
}

// round 7
// speedup vs baseline: 3.0571x; 1.2165x over previous
#include <cuda_runtime.h>
#include <cstdint>
#include <cstddef>

// Problem constants
#define BATCH   2
#define SEQ     2048
#define DIM     1024
#define HEADS   16
#define DHEAD   64
#define INNER   1024
#define ROWS    (BATCH*SEQ)   // 4096
#define QKV_N   (3*INNER)     // 3072
#define EPS     1e-5f
#define QSCALE  0.125f

// ---------------- scratch (static device globals) ---------------------------
__device__ float g_xn  [(size_t)ROWS * DIM  ];
__device__ float g_qkv [(size_t)ROWS * QKV_N];
__device__ float g_att [(size_t)ROWS * INNER];
__device__ float g_proj[(size_t)ROWS * DIM  ];
__device__ float g_wq  [(size_t)DIM * QKV_N ];
__device__ float g_wo  [(size_t)INNER * DIM ];

// ---------------- helpers ----------------------------------------------------
__device__ __forceinline__ float rnd_tf32(float x) {
    uint32_t u; asm("cvt.rna.tf32.f32 %0, %1;" : "=r"(u) : "f"(x));
    return __uint_as_float(u);
}
__device__ __forceinline__ uint32_t smem_u32(const void* p) {
    uint32_t a;
    asm("{ .reg .u64 t; cvta.to.shared.u64 t, %1; cvt.u32.u64 %0, t; }"
        : "=r"(a) : "l"(p));
    return a;
}
__device__ __forceinline__ void cpa16(uint32_t dst, const float* src) {
    asm volatile("cp.async.cg.shared.global [%0], [%1], 16;" :: "r"(dst), "l"(src));
}
__device__ __forceinline__ void cpa_commit() {
    asm volatile("cp.async.commit_group;" ::: "memory");
}
template<int N> __device__ __forceinline__ void cpa_wait() {
    asm volatile("cp.async.wait_group %0;" :: "n"(N) : "memory");
}
__device__ __forceinline__ void mma_tf32(float& d0, float& d1, float& d2, float& d3,
                                         uint32_t a0, uint32_t a1, uint32_t a2, uint32_t a3,
                                         uint32_t b0, uint32_t b1) {
    asm volatile("mma.sync.aligned.m16n8k8.row.col.f32.tf32.tf32.f32 "
                 "{%0,%1,%2,%3},{%4,%5,%6,%7},{%8,%9},{%0,%1,%2,%3};"
                 : "+f"(d0), "+f"(d1), "+f"(d2), "+f"(d3)
                 : "r"(a0), "r"(a1), "r"(a2), "r"(a3), "r"(b0), "r"(b1));
}

// ---------------- LayerNorm ---------------------------------------------------
template<bool ROUND>
__device__ __forceinline__ void ln_body(const float* __restrict__ in,
                                        const float* __restrict__ gamma,
                                        const float* __restrict__ beta,
                                        float* __restrict__ out)
{
    const int row = blockIdx.x;
    const float* xr = in + (size_t)row * DIM;
    const int t = threadIdx.x;

    float4 xv = *(const float4*)(xr + t * 4);
    float sum = xv.x + xv.y + xv.z + xv.w;
    float sq  = xv.x*xv.x + xv.y*xv.y + xv.z*xv.z + xv.w*xv.w;
    #pragma unroll
    for (int o = 16; o > 0; o >>= 1) {
        sum += __shfl_xor_sync(0xffffffffu, sum, o);
        sq  += __shfl_xor_sync(0xffffffffu, sq,  o);
    }
    __shared__ float s1[8], s2[8];
    const int warp = t >> 5;
    if ((t & 31) == 0) { s1[warp] = sum; s2[warp] = sq; }
    __syncthreads();
    float tot = 0.f, totq = 0.f;
    #pragma unroll
    for (int w = 0; w < 8; w++) { tot += s1[w]; totq += s2[w]; }
    const float mean = tot * (1.0f / DIM);
    const float var  = totq * (1.0f / DIM) - mean * mean;
    const float inv  = rsqrtf(var + EPS);
    float4 gv = *(const float4*)(gamma + t * 4);
    float4 bv = *(const float4*)(beta  + t * 4);
    float4 ov;
    ov.x = (xv.x - mean) * inv * gv.x + bv.x;
    ov.y = (xv.y - mean) * inv * gv.y + bv.y;
    ov.z = (xv.z - mean) * inv * gv.z + bv.z;
    ov.w = (xv.w - mean) * inv * gv.w + bv.w;
    if (ROUND) {
        ov.x = rnd_tf32(ov.x); ov.y = rnd_tf32(ov.y);
        ov.z = rnd_tf32(ov.z); ov.w = rnd_tf32(ov.w);
    }
    *(float4*)(out + (size_t)row * DIM + t * 4) = ov;
}
__global__ __launch_bounds__(256) void ln1_kernel(const float* __restrict__ x,
                                                  const float* __restrict__ g,
                                                  const float* __restrict__ b)
{ ln_body<true>(x, g, b, g_xn); }
__global__ __launch_bounds__(256) void ln2_kernel(const float* __restrict__ g,
                                                  const float* __restrict__ b,
                                                  float* __restrict__ out)
{ ln_body<false>(g_proj, g, b, out); }

// ---------------- elementwise tf32 rounding (weights) -----------------------
__global__ __launch_bounds__(256) void round_tf32_kernel(const float* __restrict__ in,
                                                         float* __restrict__ out, int n4)
{
    int i = blockIdx.x * blockDim.x + threadIdx.x;
    if (i < n4) {
        float4 v = ((const float4*)in)[i];
        v.x = rnd_tf32(v.x); v.y = rnd_tf32(v.y);
        v.z = rnd_tf32(v.z); v.w = rnd_tf32(v.w);
        ((float4*)out)[i] = v;
    }
}

// ---------------- tf32 HMMA GEMM: C[M,Ntot] = A[M,K] * B[K,Ntot] -------------
// BM=128, BN=256, BK=32; 256 threads = 8 warps (2x4); warp tile 64x64.
#define GBM 128
#define GBN 256
#define GBK 32
#define SA_ST 36
#define SB_ST 264
#define SA_FL (128 * SA_ST)            // 4608
#define SB_FL (GBK * SB_ST)            // 8448
#define GEMM_SMEM ((2 * SA_FL + 2 * SB_FL) * 4)  // 104448 B

template<bool RND>
__global__ __launch_bounds__(256, 1) void gemm_tf32_kernel(
    const float* __restrict__ A, const float* __restrict__ B,
    float* __restrict__ C, int Ntot, int K)
{
    extern __shared__ float sm[];
    float* sA = sm;
    float* sB = sm + 2 * SA_FL;
    const uint32_t sAu = smem_u32(sA);
    const uint32_t sBu = smem_u32(sB);

    const int tid = threadIdx.x;
    const int lane = tid & 31;
    const int wid = tid >> 5;
    const int warpM = wid >> 2;           // 0..1
    const int warpN = wid & 3;            // 0..3
    const int bm = blockIdx.y * GBM;
    const int bn = blockIdx.x * GBN;
    const int NCH = K / GBK;

    // A staging: thread covers row am, 16 floats at cols ah*16
    const int am = tid & 127;
    const int ah = tid >> 7;
    const float* aG = A + (size_t)(bm + am) * K + ah * 16;
    const uint32_t aDst = sAu + (uint32_t)(am * SA_ST + ah * 16) * 4;

    // B staging: thread covers k-row bk, 8 float4 at cols bf*4 + j*32
    const int bk = tid >> 3;
    const int bf = tid & 7;
    const float* bG = B + (size_t)bk * Ntot + bn + bf * 4;
    const uint32_t bDst = sBu + (uint32_t)(bk * SB_ST + bf * 4) * 4;

    float acc[4][8][4];
    #pragma unroll
    for (int i = 0; i < 4; i++)
        #pragma unroll
        for (int j = 0; j < 8; j++)
            #pragma unroll
            for (int r = 0; r < 4; r++) acc[i][j][r] = 0.f;

    #define GEMM_ISSUE(c, buf) do {                                           \
        const float* _ag = aG + (c) * GBK;                                     \
        const uint32_t _ad = aDst + (buf) * (SA_FL * 4);                       \
        _Pragma("unroll")                                                      \
        for (int j = 0; j < 4; j++) cpa16(_ad + j * 16, _ag + j * 4);          \
        const float* _bg = bG + (size_t)(c) * GBK * Ntot;                      \
        const uint32_t _bd = bDst + (buf) * (SB_FL * 4);                       \
        _Pragma("unroll")                                                      \
        for (int j = 0; j < 8; j++) cpa16(_bd + j * 128, _bg + j * 32);        \
    } while (0)

    GEMM_ISSUE(0, 0); cpa_commit();
    GEMM_ISSUE(1, 1); cpa_commit();

    const int arow = warpM * 64 + (lane >> 2);
    const int alo  = lane & 3;
    const int bcol = warpN * 64 + (lane >> 2);

    for (int c = 0; c < NCH; c++) {
        cpa_wait<1>();
        __syncthreads();

        const int buf = c & 1;
        const float* aS = sA + buf * SA_FL;
        const float* bS = sB + buf * SB_FL;

        #pragma unroll
        for (int ks = 0; ks < 4; ks++) {
            uint32_t af[4][4];
            #pragma unroll
            for (int mt = 0; mt < 4; mt++) {
                const float* p = aS + (arow + mt * 16) * SA_ST + ks * 8 + alo;
                af[mt][0] = __float_as_uint(p[0]);
                af[mt][1] = __float_as_uint(p[8 * SA_ST]);
                af[mt][2] = __float_as_uint(p[4]);
                af[mt][3] = __float_as_uint(p[8 * SA_ST + 4]);
            }
            uint32_t bfr[8][2];
            #pragma unroll
            for (int nt = 0; nt < 8; nt++) {
                const float* p = bS + (ks * 8 + alo) * SB_ST + bcol + nt * 8;
                bfr[nt][0] = __float_as_uint(p[0]);
                bfr[nt][1] = __float_as_uint(p[4 * SB_ST]);
            }
            #pragma unroll
            for (int mt = 0; mt < 4; mt++)
                #pragma unroll
                for (int nt = 0; nt < 8; nt++)
                    mma_tf32(acc[mt][nt][0], acc[mt][nt][1],
                             acc[mt][nt][2], acc[mt][nt][3],
                             af[mt][0], af[mt][1], af[mt][2], af[mt][3],
                             bfr[nt][0], bfr[nt][1]);
        }
        __syncthreads();

        if (c + 2 < NCH) GEMM_ISSUE(c + 2, buf);
        cpa_commit();
    }

    #pragma unroll
    for (int mt = 0; mt < 4; mt++) {
        #pragma unroll
        for (int nt = 0; nt < 8; nt++) {
            const int row = bm + warpM * 64 + mt * 16 + (lane >> 2);
            const int col = bn + warpN * 64 + nt * 8 + (lane & 3) * 2;
            float2 v0, v1;
            if (RND) {
                v0 = make_float2(rnd_tf32(acc[mt][nt][0]), rnd_tf32(acc[mt][nt][1]));
                v1 = make_float2(rnd_tf32(acc[mt][nt][2]), rnd_tf32(acc[mt][nt][3]));
            } else {
                v0 = make_float2(acc[mt][nt][0], acc[mt][nt][1]);
                v1 = make_float2(acc[mt][nt][2], acc[mt][nt][3]);
            }
            *(float2*)(C + (size_t)row * Ntot + col) = v0;
            *(float2*)(C + (size_t)(row + 8) * Ntot + col) = v1;
        }
    }
    #undef GEMM_ISSUE
}

// ---------------- tensor-core causal ReLU attention --------------------------
// 128-query tile per CTA, 256 threads (8 warps, m16 each); key tiles of 64.
// Warps 0-3 own rows qi0..qi0+64 (diag kt = 2*qt2); warps 4-7 own the next 64
// (diag kt = 2*qt2+1); a warp skips all MMA work for kt > its diagonal.
#define AQ_ST 68
#define AK_ST 68
#define AV_ST 72
#define AS_ST 68
#define OFF_Q  0                         // 128 x 68 = 8704
#define OFF_K  8704                      // 2 x (64 x 68) = 8704
#define OFF_V  17408                     // 64 x 72 = 4608
#define OFF_S  22016                     // 128 x 68 = 8704
#define ATTN_FLOATS 30720
#define ATTN_SMEM (ATTN_FLOATS * 4)      // 122880 B

__global__ __launch_bounds__(256, 1) void attn_mma_kernel()
{
    extern __shared__ float sm[];
    const uint32_t smu = smem_u32(sm);
    const int tid  = threadIdx.x;
    const int lane = tid & 31;
    const int wid  = tid >> 5;            // 0..7
    const int ly = lane >> 2;
    const int lx = lane & 3;

    const int qt2 = 15 - blockIdx.x;      // longest tiles first
    const int bh = blockIdx.y;
    const int b  = bh >> 4;
    const int h  = bh & 15;
    const int qi0 = qt2 * 128;
    const int kt_last = 2 * qt2 + 1;
    const int kt_diag = 2 * qt2 + (wid >> 2);   // this warp's diagonal key tile

    const float* qbase = g_qkv + (size_t)b * SEQ * QKV_N + h * DHEAD;
    const float* kbase = qbase + INNER;
    const float* vbase = qbase + 2 * INNER;

    const int ldr = tid >> 2;             // 0..63 (K/V staging row)
    const int ldc = (tid & 3) * 16;       // 16 floats per thread

    #define ISSUE_K(kt_, buf_) do {                                            \
        const float* _s = kbase + (size_t)((kt_) * 64 + ldr) * QKV_N + ldc;     \
        uint32_t _d = smu + (uint32_t)(OFF_K + (buf_) * 4352 + ldr * AK_ST + ldc) * 4; \
        _Pragma("unroll")                                                       \
        for (int j = 0; j < 4; j++) cpa16(_d + j * 16, _s + j * 4);             \
    } while (0)
    #define ISSUE_V(kt_) do {                                                  \
        const float* _s = vbase + (size_t)((kt_) * 64 + ldr) * QKV_N + ldc;     \
        uint32_t _d = smu + (uint32_t)(OFF_V + ldr * AV_ST + ldc) * 4;          \
        _Pragma("unroll")                                                       \
        for (int j = 0; j < 4; j++) cpa16(_d + j * 16, _s + j * 4);             \
    } while (0)

    // prefetch K(0), stage Q tile (128 rows, scaled by 2^-3: exact on tf32 grid)
    ISSUE_K(0, 0); cpa_commit();
    {
        const int qr = tid >> 1;                  // 0..127
        const int qc = (tid & 1) * 32;
        const float* src = qbase + (size_t)(qi0 + qr) * QKV_N + qc;
        float* dst = sm + OFF_Q + qr * AQ_ST + qc;
        #pragma unroll
        for (int j = 0; j < 8; j++) {
            float4 v = *(const float4*)(src + j * 4);
            v.x *= QSCALE; v.y *= QSCALE; v.z *= QSCALE; v.w *= QSCALE;
            *(float4*)(dst + j * 4) = v;
        }
    }

    float oacc[8][4];
    #pragma unroll
    for (int nt = 0; nt < 8; nt++)
        #pragma unroll
        for (int r = 0; r < 4; r++) oacc[nt][r] = 0.f;

    const float* Qw  = sm + OFF_Q + (wid * 16) * AQ_ST;
    float* shw       = sm + OFF_S + (wid * 16 + ly) * AS_ST;
    const float* shr = sm + OFF_S + (wid * 16) * AS_ST;
    const int qrow = qi0 + wid * 16 + ly;

    for (int kt = 0; kt <= kt_last; kt++) {
        cpa_wait<0>();
        __syncthreads();              // K(kt) visible; V buffer free

        ISSUE_V(kt); cpa_commit();
        if (kt < kt_last) { ISSUE_K(kt + 1, (kt + 1) & 1); cpa_commit(); }

        const bool active = (kt <= kt_diag);
        if (active) {
            // ---- S = Q K^T
            const float* Kc = sm + OFF_K + (kt & 1) * 4352;
            float sacc[8][4];
            #pragma unroll
            for (int nt = 0; nt < 8; nt++)
                #pragma unroll
                for (int r = 0; r < 4; r++) sacc[nt][r] = 0.f;

            #pragma unroll
            for (int ks = 0; ks < 8; ks++) {
                const float* ap = Qw + ly * AQ_ST + ks * 8 + lx;
                uint32_t a0 = __float_as_uint(ap[0]);
                uint32_t a1 = __float_as_uint(ap[8 * AQ_ST]);
                uint32_t a2 = __float_as_uint(ap[4]);
                uint32_t a3 = __float_as_uint(ap[8 * AQ_ST + 4]);
                #pragma unroll
                for (int nt = 0; nt < 8; nt++) {
                    const float* bp = Kc + (nt * 8 + ly) * AK_ST + ks * 8 + lx;
                    uint32_t b0 = __float_as_uint(bp[0]);
                    uint32_t b1 = __float_as_uint(bp[4]);
                    mma_tf32(sacc[nt][0], sacc[nt][1], sacc[nt][2], sacc[nt][3],
                             a0, a1, a2, a3, b0, b1);
                }
            }

            // ---- relu (+ mask on this warp's diagonal tile), rna-round, store
            if (kt < kt_diag) {
                #pragma unroll
                for (int nt = 0; nt < 8; nt++) {
                    float h0 = rnd_tf32(fmaxf(sacc[nt][0], 0.f));
                    float h1 = rnd_tf32(fmaxf(sacc[nt][1], 0.f));
                    float h2 = rnd_tf32(fmaxf(sacc[nt][2], 0.f));
                    float h3 = rnd_tf32(fmaxf(sacc[nt][3], 0.f));
                    *(float2*)(shw + nt * 8 + 2 * lx)             = make_float2(h0, h1);
                    *(float2*)(shw + 8 * AS_ST + nt * 8 + 2 * lx) = make_float2(h2, h3);
                }
            } else {
                #pragma unroll
                for (int nt = 0; nt < 8; nt++) {
                    int j0 = kt * 64 + nt * 8 + 2 * lx;
                    float v0 = (j0     <= qrow    ) ? fmaxf(sacc[nt][0], 0.f) : 0.f;
                    float v1 = (j0 + 1 <= qrow    ) ? fmaxf(sacc[nt][1], 0.f) : 0.f;
                    float v2 = (j0     <= qrow + 8) ? fmaxf(sacc[nt][2], 0.f) : 0.f;
                    float v3 = (j0 + 1 <= qrow + 8) ? fmaxf(sacc[nt][3], 0.f) : 0.f;
                    *(float2*)(shw + nt * 8 + 2 * lx) =
                        make_float2(rnd_tf32(v0), rnd_tf32(v1));
                    *(float2*)(shw + 8 * AS_ST + nt * 8 + 2 * lx) =
                        make_float2(rnd_tf32(v2), rnd_tf32(v3));
                }
            }
            __syncwarp();
        }

        if (kt < kt_last) cpa_wait<1>(); else cpa_wait<0>();
        __syncthreads();              // V visible to all warps

        if (active) {
            // ---- O += S*V
            const float* Vc = sm + OFF_V;
            #pragma unroll
            for (int ks = 0; ks < 8; ks++) {
                const float* hp = shr + ly * AS_ST + ks * 8 + lx;
                uint32_t ah0 = __float_as_uint(hp[0]);
                uint32_t ah1 = __float_as_uint(hp[8 * AS_ST]);
                uint32_t ah2 = __float_as_uint(hp[4]);
                uint32_t ah3 = __float_as_uint(hp[8 * AS_ST + 4]);
                #pragma unroll
                for (int nt = 0; nt < 8; nt++) {
                    const float* bp = Vc + (ks * 8 + lx) * AV_ST + nt * 8 + ly;
                    uint32_t b0 = __float_as_uint(bp[0]);
                    uint32_t b1 = __float_as_uint(bp[4 * AV_ST]);
                    mma_tf32(oacc[nt][0], oacc[nt][1], oacc[nt][2], oacc[nt][3],
                             ah0, ah1, ah2, ah3, b0, b1);
                }
            }
        }
    }

    // ---- store O (tf32-rounded: feeds tf32 out-projection)
    float* ob = g_att + (size_t)(b * SEQ + qi0 + wid * 16 + ly) * INNER + h * DHEAD;
    #pragma unroll
    for (int nt = 0; nt < 8; nt++) {
        *(float2*)(ob + nt * 8 + 2 * lx) =
            make_float2(rnd_tf32(oacc[nt][0]), rnd_tf32(oacc[nt][1]));
        *(float2*)(ob + (size_t)8 * INNER + nt * 8 + 2 * lx) =
            make_float2(rnd_tf32(oacc[nt][2]), rnd_tf32(oacc[nt][3]));
    }
    #undef ISSUE_K
    #undef ISSUE_V
}

// ---------------- launch -----------------------------------------------------
extern "C" void kernel_launch(void* const* d_in, const int* in_sizes, int n_in,
                              void* d_out, int out_size)
{
    const float* x     = (const float*)d_in[0];
    const float* ln1_g = (const float*)d_in[1];
    const float* ln1_b = (const float*)d_in[2];
    const float* w_qkv = (const float*)d_in[3];
    const float* w_out = (const float*)d_in[4];
    const float* ln2_g = (const float*)d_in[5];
    const float* ln2_b = (const float*)d_in[6];
    float* out = (float*)d_out;

    cudaFuncSetAttribute(attn_mma_kernel,
                         cudaFuncAttributeMaxDynamicSharedMemorySize, ATTN_SMEM);
    cudaFuncSetAttribute(gemm_tf32_kernel<true>,
                         cudaFuncAttributeMaxDynamicSharedMemorySize, GEMM_SMEM);
    cudaFuncSetAttribute(gemm_tf32_kernel<false>,
                         cudaFuncAttributeMaxDynamicSharedMemorySize, GEMM_SMEM);

    float* wq;   cudaGetSymbolAddress((void**)&wq,   g_wq);
    float* wo;   cudaGetSymbolAddress((void**)&wo,   g_wo);
    float* xn;   cudaGetSymbolAddress((void**)&xn,   g_xn);
    float* qkv;  cudaGetSymbolAddress((void**)&qkv,  g_qkv);
    float* att;  cudaGetSymbolAddress((void**)&att,  g_att);
    float* proj; cudaGetSymbolAddress((void**)&proj, g_proj);

    ln1_kernel<<<ROWS, 256>>>(x, ln1_g, ln1_b);

    {
        int n4 = (DIM * QKV_N) / 4;
        round_tf32_kernel<<<(n4 + 255) / 256, 256>>>(w_qkv, wq, n4);
    }
    {
        int n4 = (INNER * DIM) / 4;
        round_tf32_kernel<<<(n4 + 255) / 256, 256>>>(w_out, wo, n4);
    }

    gemm_tf32_kernel<true><<<dim3(QKV_N / GBN, ROWS / GBM), 256, GEMM_SMEM>>>(
        xn, wq, qkv, QKV_N, DIM);

    attn_mma_kernel<<<dim3(16, BATCH * HEADS), 256, ATTN_SMEM>>>();

    gemm_tf32_kernel<false><<<dim3(DIM / GBN, ROWS / GBM), 256, GEMM_SMEM>>>(
        att, wo, proj, DIM, INNER);

    ln2_kernel<<<ROWS, 256>>>(ln2_g, ln2_b, out);
}